// round 1
// baseline (speedup 1.0000x reference)
#include <cuda_runtime.h>

#define T_STEPS 100
#define BATCH   32
#define N_IN    1024
#define N_OUT   512
#define KDIM    (T_STEPS * BATCH)   // 3200

// Scratch (device globals — no allocation allowed in kernel_launch)
__device__ float g_preTr[KDIM * N_IN];    // [K, 1024] updated pre-trace per step
__device__ float g_postTr[KDIM * N_OUT];  // [K, 512]  updated post-trace per step

// ---------------- packed f32x2 helpers ----------------
__device__ __forceinline__ unsigned long long pack2(float lo, float hi) {
    unsigned long long r;
    asm("mov.b64 %0, {%1, %2};" : "=l"(r) : "f"(lo), "f"(hi));
    return r;
}
__device__ __forceinline__ void unpack2(unsigned long long v, float& lo, float& hi) {
    asm("mov.b64 {%0, %1}, %2;" : "=f"(lo), "=f"(hi) : "l"(v));
}
__device__ __forceinline__ unsigned long long ffma2(unsigned long long a,
                                                    unsigned long long b,
                                                    unsigned long long c) {
    unsigned long long d;
    asm("fma.rn.f32x2 %0, %1, %2, %3;" : "=l"(d) : "l"(a), "l"(b), "l"(c));
    return d;
}

// ---------------- Kernel 1: trace recurrences ----------------
// thread idx < B*N_IN handles one (b,i) pre-trace chain; the rest handle post.
__global__ void stdp_trace_kernel(const float* __restrict__ preS,
                                  const float* __restrict__ postS,
                                  const float* __restrict__ preTr0,
                                  const float* __restrict__ postTr0,
                                  float* __restrict__ out) {
    const float DECAY = 0.95122942450071400910f;  // exp(-1/20)
    const int NPRE  = BATCH * N_IN;    // 32768
    const int NPOST = BATCH * N_OUT;   // 16384
    int idx = blockIdx.x * blockDim.x + threadIdx.x;
    if (idx < NPRE) {
        float tr = preTr0[idx];
        #pragma unroll 5
        for (int t = 0; t < T_STEPS; t++) {
            tr = fmaf(tr, DECAY, preS[t * NPRE + idx]);
            g_preTr[t * NPRE + idx] = tr;
        }
        out[N_OUT * N_IN + idx] = tr;                 // final pre_trace
    } else if (idx < NPRE + NPOST) {
        int j = idx - NPRE;
        float tr = postTr0[j];
        #pragma unroll 5
        for (int t = 0; t < T_STEPS; t++) {
            tr = fmaf(tr, DECAY, postS[t * NPOST + j]);
            g_postTr[t * NPOST + j] = tr;
        }
        out[N_OUT * N_IN + NPRE + j] = tr;            // final post_trace
    }
}

// ---------------- Kernel 2: fused dual GEMM + epilogue ----------------
// C1[o,i] = sum_k postS[k,o]*preTr[k,i]   (LTP term, K=3200)
// C2[o,i] = sum_k postTr[k,o]*preS[k,i]   (LTD term)
// dw = (LR_LTP*(1-w)*C1 + LR_LTD*w*C2)/B
#define BM 64
#define BN 64
#define BK 16

__global__ __launch_bounds__(128, 1)
void stdp_gemm_kernel(const float* __restrict__ postS,   // [K, 512]
                      const float* __restrict__ preS,    // [K, 1024]
                      const float* __restrict__ weight,  // [512, 1024]
                      float* __restrict__ out) {         // dw [512, 1024]
    __shared__ __align__(16) float sA1[BK][BM];  // postS tile  (k, o)
    __shared__ __align__(16) float sA2[BK][BM];  // postTr tile
    __shared__ __align__(16) float sB1[BK][BN];  // preTr tile  (k, i)
    __shared__ __align__(16) float sB2[BK][BN];  // preS tile

    const float* preTr  = g_preTr;
    const float* postTr = g_postTr;

    const int tid = threadIdx.x;
    const int tx  = tid & 7;    // 0..7   -> n-group of 8
    const int ty  = tid >> 3;   // 0..15  -> m-group of 4
    const int m0  = ty * 4;
    const int n0  = tx * 8;
    const int bM  = blockIdx.y * BM;   // over N_OUT (grid.y = 8)
    const int bN  = blockIdx.x * BN;   // over N_IN  (grid.x = 16)

    const int lrow = tid >> 4;  // 0..7
    const int lcol = tid & 15;  // 0..15 (float4 index within 64-float row)

    unsigned long long acc1[4][4], acc2[4][4];   // [m][n-pair], 8 n per thread
    #pragma unroll
    for (int m = 0; m < 4; m++)
        #pragma unroll
        for (int p = 0; p < 4; p++) { acc1[m][p] = 0ull; acc2[m][p] = 0ull; }

    for (int kt = 0; kt < KDIM; kt += BK) {
        #pragma unroll
        for (int pss = 0; pss < 2; pss++) {
            int r = lrow + pss * 8;
            int k = kt + r;
            ((float4*)&sA1[r][0])[lcol] =
                ((const float4*)(postS  + (size_t)k * N_OUT + bM))[lcol];
            ((float4*)&sA2[r][0])[lcol] =
                ((const float4*)(postTr + (size_t)k * N_OUT + bM))[lcol];
            ((float4*)&sB1[r][0])[lcol] =
                ((const float4*)(preTr  + (size_t)k * N_IN  + bN))[lcol];
            ((float4*)&sB2[r][0])[lcol] =
                ((const float4*)(preS   + (size_t)k * N_IN  + bN))[lcol];
        }
        __syncthreads();

        #pragma unroll
        for (int kk = 0; kk < BK; kk++) {
            float4 a1 = *(const float4*)&sA1[kk][m0];
            float4 a2 = *(const float4*)&sA2[kk][m0];
            ulonglong2 t0 = *(const ulonglong2*)&sB1[kk][n0];
            ulonglong2 t1 = *(const ulonglong2*)&sB1[kk][n0 + 4];
            ulonglong2 u0 = *(const ulonglong2*)&sB2[kk][n0];
            ulonglong2 u1 = *(const ulonglong2*)&sB2[kk][n0 + 4];
            unsigned long long b1v[4] = {t0.x, t0.y, t1.x, t1.y};
            unsigned long long b2v[4] = {u0.x, u0.y, u1.x, u1.y};
            unsigned long long a1d[4] = {pack2(a1.x, a1.x), pack2(a1.y, a1.y),
                                         pack2(a1.z, a1.z), pack2(a1.w, a1.w)};
            unsigned long long a2d[4] = {pack2(a2.x, a2.x), pack2(a2.y, a2.y),
                                         pack2(a2.z, a2.z), pack2(a2.w, a2.w)};
            #pragma unroll
            for (int m = 0; m < 4; m++)
                #pragma unroll
                for (int p = 0; p < 4; p++) {
                    acc1[m][p] = ffma2(a1d[m], b1v[p], acc1[m][p]);
                    acc2[m][p] = ffma2(a2d[m], b2v[p], acc2[m][p]);
                }
        }
        __syncthreads();
    }

    // Epilogue: dw = (LR_LTP*(1-w)*C1 + LR_LTD*w*C2) / B
    const float LRP = 1e-4f, LRD = -1e-4f, invB = 1.0f / 32.0f;
    #pragma unroll
    for (int m = 0; m < 4; m++) {
        int o = bM + m0 + m;
        const float* wr   = weight + (size_t)o * N_IN + bN + n0;
        float*       orow = out    + (size_t)o * N_IN + bN + n0;
        float res[8];
        #pragma unroll
        for (int p = 0; p < 4; p++) {
            float c1l, c1h, c2l, c2h;
            unpack2(acc1[m][p], c1l, c1h);
            unpack2(acc2[m][p], c2l, c2h);
            float w0 = wr[2 * p], w1 = wr[2 * p + 1];
            res[2 * p]     = (LRP * (1.0f - w0) * c1l + LRD * w0 * c2l) * invB;
            res[2 * p + 1] = (LRP * (1.0f - w1) * c1h + LRD * w1 * c2h) * invB;
        }
        *(float4*)&orow[0] = make_float4(res[0], res[1], res[2], res[3]);
        *(float4*)&orow[4] = make_float4(res[4], res[5], res[6], res[7]);
    }
}

// ---------------- launch ----------------
extern "C" void kernel_launch(void* const* d_in, const int* in_sizes, int n_in,
                              void* d_out, int out_size) {
    const float *weight = nullptr, *preS = nullptr, *postS = nullptr;
    const float *preTr0 = nullptr, *postTr0 = nullptr;
    for (int j = 0; j < n_in; j++) {
        switch (in_sizes[j]) {
            case N_OUT * N_IN:              weight  = (const float*)d_in[j]; break;
            case T_STEPS * BATCH * N_IN:    preS    = (const float*)d_in[j]; break;
            case T_STEPS * BATCH * N_OUT:   postS   = (const float*)d_in[j]; break;
            case BATCH * N_IN:              preTr0  = (const float*)d_in[j]; break;
            case BATCH * N_OUT:             postTr0 = (const float*)d_in[j]; break;
            default: break;
        }
    }
    float* out = (float*)d_out;

    // 1) traces (also writes final pre/post traces into d_out tail)
    stdp_trace_kernel<<<192, 256>>>(preS, postS, preTr0, postTr0, out);

    // 2) fused dual GEMM + STDP epilogue -> dw at d_out head
    dim3 grid(N_IN / BN, N_OUT / BM);  // (16, 8) = 128 blocks
    stdp_gemm_kernel<<<grid, 128>>>(postS, preS, weight, out);
}